// round 1
// baseline (speedup 1.0000x reference)
#include <cuda_runtime.h>

// Qwen2 QKV projection + RoPE, fp32 baseline.
// hidden [B,S,H] @ {Wq,Wk,Wv} + bias, reshape to heads, RoPE on q,k.
// Output: q (B,NH,S,D) || k (B,NKV,S,D) || v (B,NKV,S,D), fp32.

#define B_ 2
#define S_ 4096
#define H_ 3584
#define NH_ 28
#define NKV_ 4
#define D_ 128

constexpr int M_ = B_ * S_;     // 8192
constexpr int K_ = H_;          // 3584
constexpr int BM = 128, BN = 128, BK = 16;
constexpr long QSIZE = (long)B_ * NH_ * S_ * D_;   // 29,360,128
constexpr long KSIZE = (long)B_ * NKV_ * S_ * D_;  // 4,194,304

__global__ __launch_bounds__(256, 2)
void qkv_rope_kernel(const float* __restrict__ hid,
                     const float* __restrict__ cosp,
                     const float* __restrict__ sinp,
                     const float* __restrict__ Wq, const float* __restrict__ bq,
                     const float* __restrict__ Wk, const float* __restrict__ bk,
                     const float* __restrict__ Wv, const float* __restrict__ bv,
                     float* __restrict__ out)
{
    __shared__ float As[BK][BM];   // A tile, transposed: As[k][m]
    __shared__ float Bs[BK][BN];   // B tile: Bs[k][n]

    const int by = blockIdx.y;
    const float* W; const float* bias; float* obase;
    int h, nheads, ldb; bool rope;
    if (by < NH_)            { W = Wq; bias = bq; obase = out;                 h = by;            nheads = NH_;  ldb = NH_  * D_; rope = true;  }
    else if (by < NH_ + NKV_){ W = Wk; bias = bk; obase = out + QSIZE;         h = by - NH_;      nheads = NKV_; ldb = NKV_ * D_; rope = true;  }
    else                     { W = Wv; bias = bv; obase = out + QSIZE + KSIZE; h = by - NH_-NKV_; nheads = NKV_; ldb = NKV_ * D_; rope = false; }

    const int m0 = blockIdx.x * BM;
    const int n0 = h * D_;
    const int t  = threadIdx.x;
    const int tr = t >> 4;   // 0..15: row group (8 rows each)
    const int tc = t & 15;   // 0..15: col group (4+4 paired cols)

    float acc[8][8];
    #pragma unroll
    for (int i = 0; i < 8; i++)
        #pragma unroll
        for (int j = 0; j < 8; j++) acc[i][j] = 0.f;

    for (int k0 = 0; k0 < K_; k0 += BK) {
        // ---- load A tile: 128 rows x 16 cols; 512 float4s, 2 per thread ----
        #pragma unroll
        for (int q = 0; q < 2; q++) {
            int e   = t + q * 256;
            int row = e >> 2;         // 0..127
            int c4  = e & 3;          // 0..3  (float4 column within 16)
            float4 va = *reinterpret_cast<const float4*>(
                hid + (long)(m0 + row) * H_ + k0 + c4 * 4);
            As[c4*4 + 0][row] = va.x;
            As[c4*4 + 1][row] = va.y;
            As[c4*4 + 2][row] = va.z;
            As[c4*4 + 3][row] = va.w;
        }
        // ---- load B tile: 16 rows x 128 cols; 512 float4s, 2 per thread ----
        #pragma unroll
        for (int q = 0; q < 2; q++) {
            int e   = t + q * 256;
            int row = e >> 5;         // 0..15
            int c4  = e & 31;         // 0..31
            float4 vb = *reinterpret_cast<const float4*>(
                W + (long)(k0 + row) * ldb + n0 + c4 * 4);
            *reinterpret_cast<float4*>(&Bs[row][c4 * 4]) = vb;
        }
        __syncthreads();

        // ---- compute: 8x8 microtile, cols paired (c, c+64) for RoPE ----
        #pragma unroll
        for (int kk = 0; kk < BK; kk++) {
            float a[8], bb[8];
            #pragma unroll
            for (int i = 0; i < 8; i++) a[i] = As[kk][tr * 8 + i];
            #pragma unroll
            for (int j = 0; j < 4; j++) bb[j]     = Bs[kk][tc * 4 + j];
            #pragma unroll
            for (int j = 0; j < 4; j++) bb[4 + j] = Bs[kk][64 + tc * 4 + j];
            #pragma unroll
            for (int i = 0; i < 8; i++)
                #pragma unroll
                for (int j = 0; j < 8; j++)
                    acc[i][j] += a[i] * bb[j];
        }
        __syncthreads();
    }

    // ---- epilogue: bias + RoPE + scatter to (b, h, s, d) layout ----
    float blo[4], bhi[4];
    #pragma unroll
    for (int j = 0; j < 4; j++) {
        blo[j] = bias[n0 + tc * 4 + j];
        bhi[j] = bias[n0 + 64 + tc * 4 + j];
    }

    #pragma unroll
    for (int i = 0; i < 8; i++) {
        int m  = m0 + tr * 8 + i;
        int bi = m >> 12;        // m / S_
        int s  = m & (S_ - 1);
        // cos/sin: emb = concat(freqs, freqs) -> cos[d+64] == cos[d]; only low half needed.
        float4 c4 = *reinterpret_cast<const float4*>(cosp + (long)m * D_ + tc * 4);
        float4 s4 = *reinterpret_cast<const float4*>(sinp + (long)m * D_ + tc * 4);
        float cc[4] = {c4.x, c4.y, c4.z, c4.w};
        float ss[4] = {s4.x, s4.y, s4.z, s4.w};
        float olo[4], ohi[4];
        #pragma unroll
        for (int j = 0; j < 4; j++) {
            float lo = acc[i][j]     + blo[j];   // col d       (d < 64)
            float hi = acc[i][4 + j] + bhi[j];   // col d + 64
            if (rope) {
                olo[j] = lo * cc[j] - hi * ss[j];   // q[d]*cos - q[d+64]*sin
                ohi[j] = hi * cc[j] + lo * ss[j];   // q[d+64]*cos + q[d]*sin
            } else {
                olo[j] = lo; ohi[j] = hi;
            }
        }
        float* orow = obase + ((long)(bi * nheads + h) * S_ + s) * D_;
        *reinterpret_cast<float4*>(orow + tc * 4)      = make_float4(olo[0], olo[1], olo[2], olo[3]);
        *reinterpret_cast<float4*>(orow + 64 + tc * 4) = make_float4(ohi[0], ohi[1], ohi[2], ohi[3]);
    }
}

extern "C" void kernel_launch(void* const* d_in, const int* in_sizes, int n_in,
                              void* d_out, int out_size)
{
    (void)in_sizes; (void)n_in; (void)out_size;
    const float* hid  = (const float*)d_in[0];
    const float* cosp = (const float*)d_in[1];
    const float* sinp = (const float*)d_in[2];
    const float* Wq   = (const float*)d_in[3];
    const float* bq   = (const float*)d_in[4];
    const float* Wk   = (const float*)d_in[5];
    const float* bk   = (const float*)d_in[6];
    const float* Wv   = (const float*)d_in[7];
    const float* bv   = (const float*)d_in[8];
    float* out = (float*)d_out;

    dim3 grid(M_ / BM, NH_ + 2 * NKV_);   // 64 x 36
    qkv_rope_kernel<<<grid, 256>>>(hid, cosp, sinp, Wq, bq, Wk, bk, Wv, bv, out);
}

// round 3
// speedup vs baseline: 3.2211x; 3.2211x over previous
#include <cuda_runtime.h>
#include <cuda_bf16.h>
#include <cstdint>

#define B_ 2
#define S_ 4096
#define H_ 3584
#define NH_ 28
#define NKV_ 4
#define D_ 128

constexpr int M_   = B_ * S_;                 // 8192
constexpr int K_   = H_;                      // 3584
constexpr int NTOT = (NH_ + 2 * NKV_) * D_;   // 4608
constexpr int KP   = 2 * K_;                  // packed columns (hi|lo per 32-block)
constexpr long QSIZE = (long)B_ * NH_ * S_ * D_;
constexpr long KSIZE = (long)B_ * NKV_ * S_ * D_;

constexpr int BM = 128, BN = 128;
constexpr int NC = K_ / 32;                   // 112 chunks of 32 real K
constexpr int SROW = 132;                     // epilogue stage row stride (floats)
constexpr int STAGE_BYTES = 32768;            // per stage: A 16KB + B 16KB
constexpr int SMEM_TOTAL = (BM * SROW * 4 > 2 * STAGE_BYTES) ? BM * SROW * 4 : 2 * STAGE_BYTES; // 67584

// ---------------- scratch (packed bf16 hi/lo) ----------------
__device__ __nv_bfloat16 g_Apack[(long)M_ * KP];
__device__ __nv_bfloat16 g_Bpack[(long)NTOT * KP];

// ---------------- helpers ----------------
__device__ __forceinline__ uint32_t smem_u32(const void* p) {
    uint32_t a;
    asm("{ .reg .u64 t; cvta.to.shared.u64 t, %1; cvt.u32.u64 %0, t; }" : "=r"(a) : "l"(p));
    return a;
}
__device__ __forceinline__ uint32_t swz(uint32_t off) { return off ^ ((off >> 3) & 0x70); }

__device__ __forceinline__ void cp16(uint32_t dst, const void* src) {
    asm volatile("cp.async.cg.shared.global [%0], [%1], 16;" :: "r"(dst), "l"(src));
}
#define CP_COMMIT() asm volatile("cp.async.commit_group;" ::: "memory")
#define CP_WAIT1()  asm volatile("cp.async.wait_group 1;" ::: "memory")

__device__ __forceinline__ void ldm_x4(uint32_t* r, uint32_t addr) {
    asm volatile("ldmatrix.sync.aligned.m8n8.x4.shared.b16 {%0,%1,%2,%3}, [%4];"
                 : "=r"(r[0]), "=r"(r[1]), "=r"(r[2]), "=r"(r[3]) : "r"(addr));
}
__device__ __forceinline__ void mma_bf16(float* c, const uint32_t* a, const uint32_t* b) {
    asm volatile("mma.sync.aligned.m16n8k16.row.col.f32.bf16.bf16.f32 "
                 "{%0,%1,%2,%3},{%4,%5,%6,%7},{%8,%9},{%0,%1,%2,%3};"
                 : "+f"(c[0]), "+f"(c[1]), "+f"(c[2]), "+f"(c[3])
                 : "r"(a[0]), "r"(a[1]), "r"(a[2]), "r"(a[3]), "r"(b[0]), "r"(b[1]));
}

// ---------------- conversion kernels ----------------
__global__ void convA_kernel(const float* __restrict__ hid) {
    long i4 = (long)blockIdx.x * blockDim.x + threadIdx.x;
    float4 v = reinterpret_cast<const float4*>(hid)[i4];
    int m = (int)(i4 / (K_ / 4));
    int k = (int)(i4 % (K_ / 4)) * 4;
    int blk = k >> 5, pos = k & 31;
    float x[4] = {v.x, v.y, v.z, v.w};
    __nv_bfloat16 hi[4], lo[4];
#pragma unroll
    for (int j = 0; j < 4; j++) {
        hi[j] = __float2bfloat16(x[j]);
        lo[j] = __float2bfloat16(x[j] - __bfloat162float(hi[j]));
    }
    long base = (long)m * KP + blk * 64 + pos;
    *reinterpret_cast<ushort4*>(&g_Apack[base])      = *reinterpret_cast<ushort4*>(hi);
    *reinterpret_cast<ushort4*>(&g_Apack[base + 32]) = *reinterpret_cast<ushort4*>(lo);
}

__global__ void convB_kernel(const float* __restrict__ Wq,
                             const float* __restrict__ Wk,
                             const float* __restrict__ Wv) {
    __shared__ float tile[32][33];
    int k0 = blockIdx.x * 32;
    int n0 = blockIdx.y * 32;
    const float* W; int ldw, nc;
    if (n0 < NH_ * D_)               { W = Wq; ldw = NH_ * D_;  nc = n0; }
    else if (n0 < (NH_ + NKV_) * D_) { W = Wk; ldw = NKV_ * D_; nc = n0 - NH_ * D_; }
    else                             { W = Wv; ldw = NKV_ * D_; nc = n0 - (NH_ + NKV_) * D_; }
    int tx = threadIdx.x, ty = threadIdx.y;
#pragma unroll
    for (int r = 0; r < 4; r++)
        tile[ty + r * 8][tx] = W[(long)(k0 + ty + r * 8) * ldw + nc + tx];
    __syncthreads();
#pragma unroll
    for (int r = 0; r < 4; r++) {
        int nl = ty + r * 8;
        float x = tile[tx][nl];
        __nv_bfloat16 hi = __float2bfloat16(x);
        __nv_bfloat16 lo = __float2bfloat16(x - __bfloat162float(hi));
        long base = (long)(n0 + nl) * KP + (k0 >> 5) * 64 + tx;
        g_Bpack[base]      = hi;
        g_Bpack[base + 32] = lo;
    }
}

// ---------------- fused GEMM + bias + RoPE (mma.sync) ----------------
__global__ __launch_bounds__(256, 2)
void qkv_mma_kernel(const float* __restrict__ cosp, const float* __restrict__ sinp,
                    const float* __restrict__ bq, const float* __restrict__ bk,
                    const float* __restrict__ bv, float* __restrict__ out) {
    extern __shared__ char smem[];
    const uint32_t sbase = smem_u32(smem);
    const int tid  = threadIdx.x;
    const int wid  = tid >> 5, lane = tid & 31;
    const int m0   = blockIdx.y * BM;
    const int hg   = blockIdx.x;            // one head per CTA column
    const int n0   = hg * BN;

    const int warp_m = wid & 1;             // 2 warps over M (64 rows each)
    const int warp_n = wid >> 1;            // 4 warps over N (32 cols each)

    // per-stage smem offsets
    auto abuf = [](int s) { return (uint32_t)(s * STAGE_BYTES); };
    auto bbuf = [](int s) { return (uint32_t)(s * STAGE_BYTES + 16384); };

    const __nv_bfloat16* Agb = g_Apack + (long)m0 * KP;
    const __nv_bfloat16* Bgb = g_Bpack + (long)n0 * KP;

    // ---- stage loader: 1024 uint4 each for A and B, 256 threads -> 4+4 cp.async ----
    auto load_stage = [&](int c, int s) {
        const __nv_bfloat16* Ag = Agb + (long)c * 64;
        const __nv_bfloat16* Bg = Bgb + (long)c * 64;
#pragma unroll
        for (int i = 0; i < 4; i++) {
            int e = tid + i * 256, row = e >> 3, q = e & 7;
            cp16(sbase + abuf(s) + swz(row * 128 + q * 16), Ag + (long)row * KP + q * 8);
        }
#pragma unroll
        for (int i = 0; i < 4; i++) {
            int e = tid + i * 256, row = e >> 3, q = e & 7;
            cp16(sbase + bbuf(s) + swz(row * 128 + q * 16), Bg + (long)row * KP + q * 8);
        }
    };

    float acc[4][4][4];
#pragma unroll
    for (int i = 0; i < 4; i++)
#pragma unroll
        for (int j = 0; j < 4; j++)
#pragma unroll
            for (int r = 0; r < 4; r++) acc[i][j][r] = 0.f;

    load_stage(0, 0); CP_COMMIT();
    load_stage(1, 1); CP_COMMIT();

    // precomputed lane address components
    const int a_row = lane & 15;            // A: lanes 0-15 rows, 16-31 +16B col
    const int a_cb  = (lane >> 4) * 16;
    const int b_row = ((lane >> 4) << 3) + (lane & 7);   // n row within 16
    const int b_cb  = ((lane >> 3) & 1) * 16;            // k byte sel

    for (int c = 0; c < NC; c++) {
        CP_WAIT1();
        __syncthreads();
        const int s = c & 1;
        const uint32_t ab = sbase + abuf(s);
        const uint32_t bb = sbase + bbuf(s);

#pragma unroll
        for (int ks = 0; ks < 2; ks++) {
            uint32_t ahi[4][4], alo[4][4], bhi[2][4], blo[2][4];
            // A-hi fragments (4 m16 tiles)
#pragma unroll
            for (int mt = 0; mt < 4; mt++) {
                uint32_t off = (uint32_t)(warp_m * 64 + mt * 16 + a_row) * 128 + ks * 32 + a_cb;
                ldm_x4(ahi[mt], ab + swz(off));
            }
            // B-hi fragments (2 x ldmatrix covering 4 n8 tiles)
#pragma unroll
            for (int bt = 0; bt < 2; bt++) {
                uint32_t off = (uint32_t)(warp_n * 32 + bt * 16 + b_row) * 128 + ks * 32 + b_cb;
                ldm_x4(bhi[bt], bb + swz(off));
            }
            // pass (hi, hi)
#pragma unroll
            for (int mt = 0; mt < 4; mt++)
#pragma unroll
                for (int nt = 0; nt < 4; nt++)
                    mma_bf16(acc[mt][nt], ahi[mt], &bhi[nt >> 1][(nt & 1) * 2]);
            // A-lo fragments, pass (lo, hi)
#pragma unroll
            for (int mt = 0; mt < 4; mt++) {
                uint32_t off = (uint32_t)(warp_m * 64 + mt * 16 + a_row) * 128 + 64 + ks * 32 + a_cb;
                ldm_x4(alo[mt], ab + swz(off));
            }
#pragma unroll
            for (int mt = 0; mt < 4; mt++)
#pragma unroll
                for (int nt = 0; nt < 4; nt++)
                    mma_bf16(acc[mt][nt], alo[mt], &bhi[nt >> 1][(nt & 1) * 2]);
            // B-lo fragments, pass (hi, lo)
#pragma unroll
            for (int bt = 0; bt < 2; bt++) {
                uint32_t off = (uint32_t)(warp_n * 32 + bt * 16 + b_row) * 128 + 64 + ks * 32 + b_cb;
                ldm_x4(blo[bt], bb + swz(off));
            }
#pragma unroll
            for (int mt = 0; mt < 4; mt++)
#pragma unroll
                for (int nt = 0; nt < 4; nt++)
                    mma_bf16(acc[mt][nt], ahi[mt], &blo[nt >> 1][(nt & 1) * 2]);
        }

        __syncthreads();
        if (c + 2 < NC) load_stage(c + 2, s);
        CP_COMMIT();
    }

    // ---- epilogue: accums -> smem stage ----
    float* stage = reinterpret_cast<float*>(smem);
#pragma unroll
    for (int mt = 0; mt < 4; mt++) {
#pragma unroll
        for (int nt = 0; nt < 4; nt++) {
            int row = warp_m * 64 + mt * 16 + (lane >> 2);
            int col = warp_n * 32 + nt * 8 + (lane & 3) * 2;
            *reinterpret_cast<float2*>(&stage[row * SROW + col]) =
                make_float2(acc[mt][nt][0], acc[mt][nt][1]);
            *reinterpret_cast<float2*>(&stage[(row + 8) * SROW + col]) =
                make_float2(acc[mt][nt][2], acc[mt][nt][3]);
        }
    }
    __syncthreads();

    // ---- bias + RoPE + coalesced store ----
    bool rope; const float* bias; float* ob; int nheads, hloc;
    if (hg < NH_)             { rope = true;  bias = bq; ob = out;                 nheads = NH_;  hloc = hg; }
    else if (hg < NH_ + NKV_) { rope = true;  bias = bk; ob = out + QSIZE;         nheads = NKV_; hloc = hg - NH_; }
    else                      { rope = false; bias = bv; ob = out + QSIZE + KSIZE; nheads = NKV_; hloc = hg - NH_ - NKV_; }

    const int j0 = lane * 4;                 // own columns
    const int p0 = (j0 + 64) & 127;          // partner columns
    const int d  = j0 & 63;
    float4 bo = *reinterpret_cast<const float4*>(bias + hloc * D_ + j0);
    float4 bp = *reinterpret_cast<const float4*>(bias + hloc * D_ + p0);

    for (int r = 0; r < 16; r++) {
        int row = wid * 16 + r;
        int m2 = m0 + row;
        int bi = m2 >> 12, sq = m2 & (S_ - 1);
        float4 own = *reinterpret_cast<const float4*>(&stage[row * SROW + j0]);
        float4 par = *reinterpret_cast<const float4*>(&stage[row * SROW + p0]);
        own.x += bo.x; own.y += bo.y; own.z += bo.z; own.w += bo.w;
        par.x += bp.x; par.y += bp.y; par.z += bp.z; par.w += bp.w;
        float4 o;
        if (rope) {
            float4 cc = *reinterpret_cast<const float4*>(cosp + (long)m2 * D_ + d);
            float4 ss = *reinterpret_cast<const float4*>(sinp + (long)m2 * D_ + d);
            if (lane < 16) {   // own = lo half: o = lo*c - hi*s
                o.x = own.x * cc.x - par.x * ss.x;
                o.y = own.y * cc.y - par.y * ss.y;
                o.z = own.z * cc.z - par.z * ss.z;
                o.w = own.w * cc.w - par.w * ss.w;
            } else {           // own = hi half: o = hi*c + lo*s
                o.x = own.x * cc.x + par.x * ss.x;
                o.y = own.y * cc.y + par.y * ss.y;
                o.z = own.z * cc.z + par.z * ss.z;
                o.w = own.w * cc.w + par.w * ss.w;
            }
        } else {
            o = own;
        }
        float* optr = ob + ((long)(bi * nheads + hloc) * S_ + sq) * D_;
        *reinterpret_cast<float4*>(optr + j0) = o;
    }
}

// ---------------- launch ----------------
extern "C" void kernel_launch(void* const* d_in, const int* in_sizes, int n_in,
                              void* d_out, int out_size) {
    (void)in_sizes; (void)n_in; (void)out_size;
    const float* hid  = (const float*)d_in[0];
    const float* cosp = (const float*)d_in[1];
    const float* sinp = (const float*)d_in[2];
    const float* Wq   = (const float*)d_in[3];
    const float* bq   = (const float*)d_in[4];
    const float* Wk   = (const float*)d_in[5];
    const float* bk   = (const float*)d_in[6];
    const float* Wv   = (const float*)d_in[7];
    const float* bv   = (const float*)d_in[8];
    float* out = (float*)d_out;

    cudaFuncSetAttribute(qkv_mma_kernel, cudaFuncAttributeMaxDynamicSharedMemorySize, SMEM_TOTAL);

    convA_kernel<<<(M_ * K_ / 4) / 256, 256>>>(hid);
    convB_kernel<<<dim3(K_ / 32, NTOT / 32), dim3(32, 8)>>>(Wq, Wk, Wv);
    qkv_mma_kernel<<<dim3(NTOT / BN, M_ / BM), 256, SMEM_TOTAL>>>(cosp, sinp, bq, bk, bv, out);
}

// round 4
// speedup vs baseline: 3.3429x; 1.0378x over previous
#include <cuda_runtime.h>
#include <cuda_bf16.h>
#include <cstdint>

#define B_ 2
#define S_ 4096
#define H_ 3584
#define NH_ 28
#define NKV_ 4
#define D_ 128

constexpr int M_   = B_ * S_;                 // 8192
constexpr int K_   = H_;                      // 3584
constexpr int NTOT = (NH_ + 2 * NKV_) * D_;   // 4608
constexpr int KP   = 2 * K_;                  // packed columns (hi|lo per 32-block)
constexpr long QSIZE = (long)B_ * NH_ * S_ * D_;
constexpr long KSIZE = (long)B_ * NKV_ * S_ * D_;

constexpr int BM = 128, BN = 128;
constexpr int NC = K_ / 32;                   // 112 chunks of 32 real K
constexpr int NSTAGE = 3;
constexpr int STAGE_BYTES = 32768;            // A 16KB + B 16KB per stage
constexpr int SROW = 132;                     // epilogue stage row stride (floats)
constexpr int SMEM_TOTAL = (NSTAGE * STAGE_BYTES > BM * SROW * 4)
                         ? NSTAGE * STAGE_BYTES : BM * SROW * 4;   // 98304

// ---------------- scratch (packed bf16 hi/lo) ----------------
__device__ __nv_bfloat16 g_Apack[(long)M_ * KP];
__device__ __nv_bfloat16 g_Bpack[(long)NTOT * KP];

// ---------------- helpers ----------------
__device__ __forceinline__ uint32_t smem_u32(const void* p) {
    uint32_t a;
    asm("{ .reg .u64 t; cvta.to.shared.u64 t, %1; cvt.u32.u64 %0, t; }" : "=r"(a) : "l"(p));
    return a;
}
__device__ __forceinline__ uint32_t swz(uint32_t off) { return off ^ ((off >> 3) & 0x70); }

__device__ __forceinline__ void cp16(uint32_t dst, const void* src) {
    asm volatile("cp.async.cg.shared.global [%0], [%1], 16;" :: "r"(dst), "l"(src));
}
#define CP_COMMIT() asm volatile("cp.async.commit_group;" ::: "memory")
#define CP_WAIT1()  asm volatile("cp.async.wait_group 1;" ::: "memory")
#define CP_WAIT0()  asm volatile("cp.async.wait_group 0;" ::: "memory")

__device__ __forceinline__ void ldm_x4(uint32_t* r, uint32_t addr) {
    asm volatile("ldmatrix.sync.aligned.m8n8.x4.shared.b16 {%0,%1,%2,%3}, [%4];"
                 : "=r"(r[0]), "=r"(r[1]), "=r"(r[2]), "=r"(r[3]) : "r"(addr));
}
__device__ __forceinline__ void mma_bf16(float* c, const uint32_t* a, const uint32_t* b) {
    asm volatile("mma.sync.aligned.m16n8k16.row.col.f32.bf16.bf16.f32 "
                 "{%0,%1,%2,%3},{%4,%5,%6,%7},{%8,%9},{%0,%1,%2,%3};"
                 : "+f"(c[0]), "+f"(c[1]), "+f"(c[2]), "+f"(c[3])
                 : "r"(a[0]), "r"(a[1]), "r"(a[2]), "r"(a[3]), "r"(b[0]), "r"(b[1]));
}

// ---------------- conversion kernels ----------------
__global__ void convA_kernel(const float* __restrict__ hid) {
    long i4 = (long)blockIdx.x * blockDim.x + threadIdx.x;
    float4 v = reinterpret_cast<const float4*>(hid)[i4];
    int m = (int)(i4 / (K_ / 4));
    int k = (int)(i4 % (K_ / 4)) * 4;
    int blk = k >> 5, pos = k & 31;
    float x[4] = {v.x, v.y, v.z, v.w};
    __nv_bfloat16 hi[4], lo[4];
#pragma unroll
    for (int j = 0; j < 4; j++) {
        hi[j] = __float2bfloat16(x[j]);
        lo[j] = __float2bfloat16(x[j] - __bfloat162float(hi[j]));
    }
    long base = (long)m * KP + blk * 64 + pos;
    *reinterpret_cast<ushort4*>(&g_Apack[base])      = *reinterpret_cast<ushort4*>(hi);
    *reinterpret_cast<ushort4*>(&g_Apack[base + 32]) = *reinterpret_cast<ushort4*>(lo);
}

__global__ void convB_kernel(const float* __restrict__ Wq,
                             const float* __restrict__ Wk,
                             const float* __restrict__ Wv) {
    __shared__ float tile[32][33];
    int k0 = blockIdx.x * 32;
    int n0 = blockIdx.y * 32;
    const float* W; int ldw, nc;
    if (n0 < NH_ * D_)               { W = Wq; ldw = NH_ * D_;  nc = n0; }
    else if (n0 < (NH_ + NKV_) * D_) { W = Wk; ldw = NKV_ * D_; nc = n0 - NH_ * D_; }
    else                             { W = Wv; ldw = NKV_ * D_; nc = n0 - (NH_ + NKV_) * D_; }
    int tx = threadIdx.x, ty = threadIdx.y;
#pragma unroll
    for (int r = 0; r < 4; r++)
        tile[ty + r * 8][tx] = W[(long)(k0 + ty + r * 8) * ldw + nc + tx];
    __syncthreads();
#pragma unroll
    for (int r = 0; r < 4; r++) {
        int nl = ty + r * 8;
        float x = tile[tx][nl];
        __nv_bfloat16 hi = __float2bfloat16(x);
        __nv_bfloat16 lo = __float2bfloat16(x - __bfloat162float(hi));
        long base = (long)(n0 + nl) * KP + (k0 >> 5) * 64 + tx;
        g_Bpack[base]      = hi;
        g_Bpack[base + 32] = lo;
    }
}

// ---------------- fused GEMM + bias + RoPE (mma.sync, 64x64 warp tiles) ----------------
__global__ __launch_bounds__(128, 2)
void qkv_mma_kernel(const float* __restrict__ cosp, const float* __restrict__ sinp,
                    const float* __restrict__ bq, const float* __restrict__ bk,
                    const float* __restrict__ bv, float* __restrict__ out) {
    extern __shared__ char smem[];
    const uint32_t sbase = smem_u32(smem);
    const int tid  = threadIdx.x;
    const int wid  = tid >> 5, lane = tid & 31;
    const int m0   = blockIdx.y * BM;
    const int hg   = blockIdx.x;            // one head per CTA
    const int n0   = hg * BN;

    const int warp_m = wid & 1;             // 2 warps over M (64 rows each)
    const int warp_n = wid >> 1;            // 2 warps over N (64 cols each)

    const __nv_bfloat16* Agb = g_Apack + (long)m0 * KP;
    const __nv_bfloat16* Bgb = g_Bpack + (long)n0 * KP;

    // stage loader: A 1024 x 16B + B 1024 x 16B over 128 threads -> 8+8 cp.async each
    auto load_stage = [&](int c, int s) {
        const uint32_t ab = sbase + (uint32_t)(s * STAGE_BYTES);
        const uint32_t bb = ab + 16384;
        const __nv_bfloat16* Ag = Agb + (long)c * 64;
        const __nv_bfloat16* Bg = Bgb + (long)c * 64;
#pragma unroll
        for (int i = 0; i < 8; i++) {
            int e = tid + i * 128, row = e >> 3, q = e & 7;
            cp16(ab + swz(row * 128 + q * 16), Ag + (long)row * KP + q * 8);
        }
#pragma unroll
        for (int i = 0; i < 8; i++) {
            int e = tid + i * 128, row = e >> 3, q = e & 7;
            cp16(bb + swz(row * 128 + q * 16), Bg + (long)row * KP + q * 8);
        }
    };

    float acc[4][8][4];
#pragma unroll
    for (int i = 0; i < 4; i++)
#pragma unroll
        for (int j = 0; j < 8; j++)
#pragma unroll
            for (int r = 0; r < 4; r++) acc[i][j][r] = 0.f;

    load_stage(0, 0); CP_COMMIT();
    load_stage(1, 1); CP_COMMIT();

    const int a_row = lane & 15;
    const int a_cb  = (lane >> 4) * 16;
    const int b_row = ((lane >> 4) << 3) + (lane & 7);
    const int b_cb  = ((lane >> 3) & 1) * 16;

    for (int c = 0; c < NC; c++) {
        CP_WAIT1();
        __syncthreads();                    // stage c ready; all warps done with c-1

        if (c + 2 < NC) load_stage(c + 2, (c + 2) % NSTAGE);
        CP_COMMIT();

        const uint32_t ab = sbase + (uint32_t)((c % NSTAGE) * STAGE_BYTES);
        const uint32_t bb = ab + 16384;

#pragma unroll
        for (int ks = 0; ks < 2; ks++) {
            uint32_t af[4][4], bf[4][4], af2[4][4];
            // A-hi, B-hi
#pragma unroll
            for (int mt = 0; mt < 4; mt++) {
                uint32_t off = (uint32_t)(warp_m * 64 + mt * 16 + a_row) * 128 + ks * 32 + a_cb;
                ldm_x4(af[mt], ab + swz(off));
            }
#pragma unroll
            for (int bt = 0; bt < 4; bt++) {
                uint32_t off = (uint32_t)(warp_n * 64 + bt * 16 + b_row) * 128 + ks * 32 + b_cb;
                ldm_x4(bf[bt], bb + swz(off));
            }
            // pass 1: hi*hi
#pragma unroll
            for (int mt = 0; mt < 4; mt++)
#pragma unroll
                for (int nt = 0; nt < 8; nt++)
                    mma_bf16(acc[mt][nt], af[mt], &bf[nt >> 1][(nt & 1) * 2]);
            // A-lo, pass 2: lo*hi
#pragma unroll
            for (int mt = 0; mt < 4; mt++) {
                uint32_t off = (uint32_t)(warp_m * 64 + mt * 16 + a_row) * 128 + 64 + ks * 32 + a_cb;
                ldm_x4(af2[mt], ab + swz(off));
            }
#pragma unroll
            for (int mt = 0; mt < 4; mt++)
#pragma unroll
                for (int nt = 0; nt < 8; nt++)
                    mma_bf16(acc[mt][nt], af2[mt], &bf[nt >> 1][(nt & 1) * 2]);
            // B-lo (overwrite bf), pass 3: hi*lo
#pragma unroll
            for (int bt = 0; bt < 4; bt++) {
                uint32_t off = (uint32_t)(warp_n * 64 + bt * 16 + b_row) * 128 + 64 + ks * 32 + b_cb;
                ldm_x4(bf[bt], bb + swz(off));
            }
#pragma unroll
            for (int mt = 0; mt < 4; mt++)
#pragma unroll
                for (int nt = 0; nt < 8; nt++)
                    mma_bf16(acc[mt][nt], af[mt], &bf[nt >> 1][(nt & 1) * 2]);
        }
    }

    CP_WAIT0();
    __syncthreads();

    // ---- epilogue: accums -> smem stage ----
    float* stage = reinterpret_cast<float*>(smem);
#pragma unroll
    for (int mt = 0; mt < 4; mt++) {
#pragma unroll
        for (int nt = 0; nt < 8; nt++) {
            int row = warp_m * 64 + mt * 16 + (lane >> 2);
            int col = warp_n * 64 + nt * 8 + (lane & 3) * 2;
            *reinterpret_cast<float2*>(&stage[row * SROW + col]) =
                make_float2(acc[mt][nt][0], acc[mt][nt][1]);
            *reinterpret_cast<float2*>(&stage[(row + 8) * SROW + col]) =
                make_float2(acc[mt][nt][2], acc[mt][nt][3]);
        }
    }
    __syncthreads();

    // ---- bias + RoPE + coalesced store (one head) ----
    bool rope; const float* bias; float* ob; int nheads, hloc;
    if (hg < NH_)             { rope = true;  bias = bq; ob = out;                 nheads = NH_;  hloc = hg; }
    else if (hg < NH_ + NKV_) { rope = true;  bias = bk; ob = out + QSIZE;         nheads = NKV_; hloc = hg - NH_; }
    else                      { rope = false; bias = bv; ob = out + QSIZE + KSIZE; nheads = NKV_; hloc = hg - NH_ - NKV_; }

    const int j0 = lane * 4;                 // own columns
    const int p0 = (j0 + 64) & 127;          // partner columns
    const int d  = j0 & 63;
    float4 bo = *reinterpret_cast<const float4*>(bias + hloc * D_ + j0);
    float4 bp = *reinterpret_cast<const float4*>(bias + hloc * D_ + p0);

    for (int r = 0; r < 32; r++) {
        int row = wid * 32 + r;
        int m2 = m0 + row;
        int bi = m2 >> 12, sq = m2 & (S_ - 1);
        float4 own = *reinterpret_cast<const float4*>(&stage[row * SROW + j0]);
        float4 par = *reinterpret_cast<const float4*>(&stage[row * SROW + p0]);
        own.x += bo.x; own.y += bo.y; own.z += bo.z; own.w += bo.w;
        par.x += bp.x; par.y += bp.y; par.z += bp.z; par.w += bp.w;
        float4 o;
        if (rope) {
            float4 cc = *reinterpret_cast<const float4*>(cosp + (long)m2 * D_ + d);
            float4 ss = *reinterpret_cast<const float4*>(sinp + (long)m2 * D_ + d);
            if (lane < 16) {   // own = lo half: o = lo*c - hi*s
                o.x = own.x * cc.x - par.x * ss.x;
                o.y = own.y * cc.y - par.y * ss.y;
                o.z = own.z * cc.z - par.z * ss.z;
                o.w = own.w * cc.w - par.w * ss.w;
            } else {           // own = hi half: o = hi*c + lo*s
                o.x = own.x * cc.x + par.x * ss.x;
                o.y = own.y * cc.y + par.y * ss.y;
                o.z = own.z * cc.z + par.z * ss.z;
                o.w = own.w * cc.w + par.w * ss.w;
            }
        } else {
            o = own;
        }
        float* optr = ob + ((long)(bi * nheads + hloc) * S_ + sq) * D_;
        *reinterpret_cast<float4*>(optr + j0) = o;
    }
}

// ---------------- launch ----------------
extern "C" void kernel_launch(void* const* d_in, const int* in_sizes, int n_in,
                              void* d_out, int out_size) {
    (void)in_sizes; (void)n_in; (void)out_size;
    const float* hid  = (const float*)d_in[0];
    const float* cosp = (const float*)d_in[1];
    const float* sinp = (const float*)d_in[2];
    const float* Wq   = (const float*)d_in[3];
    const float* bq   = (const float*)d_in[4];
    const float* Wk   = (const float*)d_in[5];
    const float* bk   = (const float*)d_in[6];
    const float* Wv   = (const float*)d_in[7];
    const float* bv   = (const float*)d_in[8];
    float* out = (float*)d_out;

    cudaFuncSetAttribute(qkv_mma_kernel, cudaFuncAttributeMaxDynamicSharedMemorySize, SMEM_TOTAL);

    convA_kernel<<<(M_ * K_ / 4) / 256, 256>>>(hid);
    convB_kernel<<<dim3(K_ / 32, NTOT / 32), dim3(32, 8)>>>(Wq, Wk, Wv);
    qkv_mma_kernel<<<dim3(NTOT / BN, M_ / BM), 128, SMEM_TOTAL>>>(cosp, sinp, bq, bk, bv, out);
}

// round 5
// speedup vs baseline: 4.1319x; 1.2360x over previous
#include <cuda_runtime.h>
#include <cuda_fp16.h>
#include <cstdint>

#define B_ 2
#define S_ 4096
#define H_ 3584
#define NH_ 28
#define NKV_ 4
#define D_ 128

constexpr int M_   = B_ * S_;                 // 8192
constexpr int K_   = H_;                      // 3584
constexpr int NTOT = (NH_ + 2 * NKV_) * D_;   // 4608
constexpr int KP   = 2 * K_;                  // B packed cols (hi|lo per 32-block)
constexpr long QSIZE = (long)B_ * NH_ * S_ * D_;
constexpr long KSIZE = (long)B_ * NKV_ * S_ * D_;

constexpr int BM = 256, BN = 128;
constexpr int NC = K_ / 32;                   // 112 chunks of 32 real K
constexpr int NSTAGE = 4;
constexpr int STAGE_BYTES = 32768;            // A 16KB (256x64B) + B 16KB (128x128B)
constexpr int SROW = 132;
constexpr int SMEM_TOTAL = (NSTAGE * STAGE_BYTES > BM * SROW * 4)
                         ? NSTAGE * STAGE_BYTES : BM * SROW * 4;  // 135168

// ---------------- scratch ----------------
__device__ __half g_Apack[(long)M_ * K_];     // plain [m][k] fp16 (hi only)
__device__ __half g_Bpack[(long)NTOT * KP];   // [n][blk*64 + islo*32 + pos] fp16 hi|lo

// ---------------- helpers ----------------
__device__ __forceinline__ uint32_t smem_u32(const void* p) {
    uint32_t a;
    asm("{ .reg .u64 t; cvta.to.shared.u64 t, %1; cvt.u32.u64 %0, t; }" : "=r"(a) : "l"(p));
    return a;
}
__device__ __forceinline__ uint32_t swz128(uint32_t off) { return off ^ ((off >> 3) & 0x70); }
__device__ __forceinline__ uint32_t swz64(uint32_t off)  { return off ^ ((off >> 3) & 0x30); }

__device__ __forceinline__ void cp16(uint32_t dst, const void* src) {
    asm volatile("cp.async.cg.shared.global [%0], [%1], 16;" :: "r"(dst), "l"(src));
}
#define CP_COMMIT() asm volatile("cp.async.commit_group;" ::: "memory")
#define CP_WAIT2()  asm volatile("cp.async.wait_group 2;" ::: "memory")
#define CP_WAIT0()  asm volatile("cp.async.wait_group 0;" ::: "memory")

__device__ __forceinline__ void ldm_x4(uint32_t* r, uint32_t addr) {
    asm volatile("ldmatrix.sync.aligned.m8n8.x4.shared.b16 {%0,%1,%2,%3}, [%4];"
                 : "=r"(r[0]), "=r"(r[1]), "=r"(r[2]), "=r"(r[3]) : "r"(addr));
}
__device__ __forceinline__ void mma_f16(float* c, const uint32_t* a, const uint32_t* b) {
    asm volatile("mma.sync.aligned.m16n8k16.row.col.f32.f16.f16.f32 "
                 "{%0,%1,%2,%3},{%4,%5,%6,%7},{%8,%9},{%0,%1,%2,%3};"
                 : "+f"(c[0]), "+f"(c[1]), "+f"(c[2]), "+f"(c[3])
                 : "r"(a[0]), "r"(a[1]), "r"(a[2]), "r"(a[3]), "r"(b[0]), "r"(b[1]));
}

// ---------------- conversion kernels ----------------
__global__ void convA_kernel(const float* __restrict__ hid) {
    long i4 = (long)blockIdx.x * blockDim.x + threadIdx.x;   // over M_*K_/4
    float4 v = reinterpret_cast<const float4*>(hid)[i4];
    __half h[4] = {__float2half_rn(v.x), __float2half_rn(v.y),
                   __float2half_rn(v.z), __float2half_rn(v.w)};
    *reinterpret_cast<ushort4*>(&g_Apack[i4 * 4]) = *reinterpret_cast<ushort4*>(h);
}

__global__ void convB_kernel(const float* __restrict__ Wq,
                             const float* __restrict__ Wk,
                             const float* __restrict__ Wv) {
    __shared__ float tile[32][33];
    int k0 = blockIdx.x * 32;
    int n0 = blockIdx.y * 32;
    const float* W; int ldw, nc;
    if (n0 < NH_ * D_)               { W = Wq; ldw = NH_ * D_;  nc = n0; }
    else if (n0 < (NH_ + NKV_) * D_) { W = Wk; ldw = NKV_ * D_; nc = n0 - NH_ * D_; }
    else                             { W = Wv; ldw = NKV_ * D_; nc = n0 - (NH_ + NKV_) * D_; }
    int tx = threadIdx.x, ty = threadIdx.y;
#pragma unroll
    for (int r = 0; r < 4; r++)
        tile[ty + r * 8][tx] = W[(long)(k0 + ty + r * 8) * ldw + nc + tx];
    __syncthreads();
#pragma unroll
    for (int r = 0; r < 4; r++) {
        int nl = ty + r * 8;
        float x = tile[tx][nl];
        __half hi = __float2half_rn(x);
        __half lo = __float2half_rn(x - __half2float(hi));
        long base = (long)(n0 + nl) * KP + (k0 >> 5) * 64 + tx;
        g_Bpack[base]      = hi;
        g_Bpack[base + 32] = lo;
    }
}

// ---------------- fused GEMM + bias + RoPE ----------------
__global__ __launch_bounds__(256, 1)
void qkv_mma_kernel(const float* __restrict__ cosp, const float* __restrict__ sinp,
                    const float* __restrict__ bq, const float* __restrict__ bk,
                    const float* __restrict__ bv, float* __restrict__ out) {
    extern __shared__ char smem[];
    const uint32_t sbase = smem_u32(smem);
    const int tid  = threadIdx.x;
    const int wid  = tid >> 5, lane = tid & 31;
    const int m0   = blockIdx.y * BM;
    const int hg   = blockIdx.x;              // one head per CTA
    const int n0   = hg * BN;

    const int warp_m = wid & 3;               // 4 warps over M (64 rows each)
    const int warp_n = wid >> 2;              // 2 warps over N (64 cols each)

    const __half* Agb = g_Apack + (long)m0 * K_;
    const __half* Bgb = g_Bpack + (long)n0 * KP;

    // stage loader: A 1024x16B (SW64) + B 1024x16B (SW128), 256 threads -> 4+4 each
    auto load_stage = [&](int c, int s) {
        const uint32_t ab = sbase + (uint32_t)(s * STAGE_BYTES);
        const uint32_t bb = ab + 16384;
        const __half* Ag = Agb + (long)c * 32;
        const __half* Bg = Bgb + (long)c * 64;
#pragma unroll
        for (int i = 0; i < 4; i++) {
            int e = tid + i * 256, row = e >> 2, q = e & 3;   // 256 rows x 4 units
            cp16(ab + swz64(row * 64 + q * 16), Ag + (long)row * K_ + q * 8);
        }
#pragma unroll
        for (int i = 0; i < 4; i++) {
            int e = tid + i * 256, row = e >> 3, q = e & 7;   // 128 rows x 8 units
            cp16(bb + swz128(row * 128 + q * 16), Bg + (long)row * KP + q * 8);
        }
    };

    float acc[4][8][4];
#pragma unroll
    for (int i = 0; i < 4; i++)
#pragma unroll
        for (int j = 0; j < 8; j++)
#pragma unroll
            for (int r = 0; r < 4; r++) acc[i][j][r] = 0.f;

    load_stage(0, 0); CP_COMMIT();
    load_stage(1, 1); CP_COMMIT();
    load_stage(2, 2); CP_COMMIT();

    const int a_row = lane & 15;
    const int a_cb  = (lane >> 4) * 16;
    const int b_row = ((lane >> 4) << 3) + (lane & 7);
    const int b_cb  = ((lane >> 3) & 1) * 16;

    for (int c = 0; c < NC; c++) {
        CP_WAIT2();
        __syncthreads();                      // stage c ready; all warps done with stage c-1

        if (c + 3 < NC) load_stage(c + 3, (c + 3) & 3);
        CP_COMMIT();

        const uint32_t ab = sbase + (uint32_t)((c & 3) * STAGE_BYTES);
        const uint32_t bb = ab + 16384;

#pragma unroll
        for (int ks = 0; ks < 2; ks++) {
            uint32_t af[4][4], bf[4][4];
            // A-hi fragments (64B rows, SW64)
#pragma unroll
            for (int mt = 0; mt < 4; mt++) {
                uint32_t off = (uint32_t)(warp_m * 64 + mt * 16 + a_row) * 64 + ks * 32 + a_cb;
                ldm_x4(af[mt], ab + swz64(off));
            }
            // B-hi fragments
#pragma unroll
            for (int bt = 0; bt < 4; bt++) {
                uint32_t off = (uint32_t)(warp_n * 64 + bt * 16 + b_row) * 128 + ks * 32 + b_cb;
                ldm_x4(bf[bt], bb + swz128(off));
            }
            // pass 1: a_hi * b_hi
#pragma unroll
            for (int mt = 0; mt < 4; mt++)
#pragma unroll
                for (int nt = 0; nt < 8; nt++)
                    mma_f16(acc[mt][nt], af[mt], &bf[nt >> 1][(nt & 1) * 2]);
            // B-lo fragments (overwrite bf), pass 2: a_hi * b_lo
#pragma unroll
            for (int bt = 0; bt < 4; bt++) {
                uint32_t off = (uint32_t)(warp_n * 64 + bt * 16 + b_row) * 128 + 64 + ks * 32 + b_cb;
                ldm_x4(bf[bt], bb + swz128(off));
            }
#pragma unroll
            for (int mt = 0; mt < 4; mt++)
#pragma unroll
                for (int nt = 0; nt < 8; nt++)
                    mma_f16(acc[mt][nt], af[mt], &bf[nt >> 1][(nt & 1) * 2]);
        }
    }

    CP_WAIT0();
    __syncthreads();

    // ---- epilogue: accums -> smem stage ----
    float* stage = reinterpret_cast<float*>(smem);
#pragma unroll
    for (int mt = 0; mt < 4; mt++) {
#pragma unroll
        for (int nt = 0; nt < 8; nt++) {
            int row = warp_m * 64 + mt * 16 + (lane >> 2);
            int col = warp_n * 64 + nt * 8 + (lane & 3) * 2;
            *reinterpret_cast<float2*>(&stage[row * SROW + col]) =
                make_float2(acc[mt][nt][0], acc[mt][nt][1]);
            *reinterpret_cast<float2*>(&stage[(row + 8) * SROW + col]) =
                make_float2(acc[mt][nt][2], acc[mt][nt][3]);
        }
    }
    __syncthreads();

    // ---- bias + RoPE + coalesced store (one head) ----
    bool rope; const float* bias; float* ob; int nheads, hloc;
    if (hg < NH_)             { rope = true;  bias = bq; ob = out;                 nheads = NH_;  hloc = hg; }
    else if (hg < NH_ + NKV_) { rope = true;  bias = bk; ob = out + QSIZE;         nheads = NKV_; hloc = hg - NH_; }
    else                      { rope = false; bias = bv; ob = out + QSIZE + KSIZE; nheads = NKV_; hloc = hg - NH_ - NKV_; }

    const int j0 = lane * 4;                 // own columns
    const int p0 = (j0 + 64) & 127;          // partner columns
    const int d  = j0 & 63;
    float4 bo = *reinterpret_cast<const float4*>(bias + hloc * D_ + j0);
    float4 bp = *reinterpret_cast<const float4*>(bias + hloc * D_ + p0);

    for (int r = 0; r < 32; r++) {
        int row = wid * 32 + r;              // 8 warps x 32 rows = 256
        int m2 = m0 + row;
        int bi = m2 >> 12, sq = m2 & (S_ - 1);
        float4 own = *reinterpret_cast<const float4*>(&stage[row * SROW + j0]);
        float4 par = *reinterpret_cast<const float4*>(&stage[row * SROW + p0]);
        own.x += bo.x; own.y += bo.y; own.z += bo.z; own.w += bo.w;
        par.x += bp.x; par.y += bp.y; par.z += bp.z; par.w += bp.w;
        float4 o;
        if (rope) {
            float4 cc = *reinterpret_cast<const float4*>(cosp + (long)m2 * D_ + d);
            float4 ss = *reinterpret_cast<const float4*>(sinp + (long)m2 * D_ + d);
            if (lane < 16) {   // own = lo half: o = lo*c - hi*s
                o.x = own.x * cc.x - par.x * ss.x;
                o.y = own.y * cc.y - par.y * ss.y;
                o.z = own.z * cc.z - par.z * ss.z;
                o.w = own.w * cc.w - par.w * ss.w;
            } else {           // own = hi half: o = hi*c + lo*s
                o.x = own.x * cc.x + par.x * ss.x;
                o.y = own.y * cc.y + par.y * ss.y;
                o.z = own.z * cc.z + par.z * ss.z;
                o.w = own.w * cc.w + par.w * ss.w;
            }
        } else {
            o = own;
        }
        float* optr = ob + ((long)(bi * nheads + hloc) * S_ + sq) * D_;
        *reinterpret_cast<float4*>(optr + j0) = o;
    }
}

// ---------------- launch ----------------
extern "C" void kernel_launch(void* const* d_in, const int* in_sizes, int n_in,
                              void* d_out, int out_size) {
    (void)in_sizes; (void)n_in; (void)out_size;
    const float* hid  = (const float*)d_in[0];
    const float* cosp = (const float*)d_in[1];
    const float* sinp = (const float*)d_in[2];
    const float* Wq   = (const float*)d_in[3];
    const float* bq   = (const float*)d_in[4];
    const float* Wk   = (const float*)d_in[5];
    const float* bk   = (const float*)d_in[6];
    const float* Wv   = (const float*)d_in[7];
    const float* bv   = (const float*)d_in[8];
    float* out = (float*)d_out;

    cudaFuncSetAttribute(qkv_mma_kernel, cudaFuncAttributeMaxDynamicSharedMemorySize, SMEM_TOTAL);

    convA_kernel<<<(M_ * K_ / 4) / 256, 256>>>(hid);
    convB_kernel<<<dim3(K_ / 32, NTOT / 32), dim3(32, 8)>>>(Wq, Wk, Wv);
    qkv_mma_kernel<<<dim3(NTOT / BN, M_ / BM), 256, SMEM_TOTAL>>>(cosp, sinp, bq, bk, bv, out);
}

// round 6
// speedup vs baseline: 4.2501x; 1.0286x over previous
#include <cuda_runtime.h>
#include <cuda_fp16.h>
#include <cstdint>

#define B_ 2
#define S_ 4096
#define H_ 3584
#define NH_ 28
#define NKV_ 4
#define D_ 128

constexpr int M_   = B_ * S_;                 // 8192
constexpr int K_   = H_;                      // 3584
constexpr int NTOT = (NH_ + 2 * NKV_) * D_;   // 4608
constexpr int KP   = 2 * K_;                  // B packed cols (hi|lo per 32-block)
constexpr long QSIZE = (long)B_ * NH_ * S_ * D_;
constexpr long KSIZE = (long)B_ * NKV_ * S_ * D_;

constexpr int BM = 256, BN = 128;
constexpr int NC = K_ / 32;                   // 112 chunks of 32 real K
constexpr int NSTAGE = 4;
constexpr int STAGE_BYTES = 32768;            // A 16KB (256x64B) + B 16KB (128x128B)
constexpr int SROW = 132;
constexpr int SMEM_TOTAL = (NSTAGE * STAGE_BYTES > BM * SROW * 4)
                         ? NSTAGE * STAGE_BYTES : BM * SROW * 4;  // 135168

// ---------------- scratch ----------------
__device__ __half g_Apack[(long)M_ * K_];     // plain [m][k] fp16 (hi only)
__device__ __half g_Bpack[(long)NTOT * KP];   // [n][blk*64 + islo*32 + pos] fp16 hi|lo

// ---------------- helpers ----------------
__device__ __forceinline__ uint32_t smem_u32(const void* p) {
    uint32_t a;
    asm("{ .reg .u64 t; cvta.to.shared.u64 t, %1; cvt.u32.u64 %0, t; }" : "=r"(a) : "l"(p));
    return a;
}
__device__ __forceinline__ uint32_t swz128(uint32_t off) { return off ^ ((off >> 3) & 0x70); }
__device__ __forceinline__ uint32_t swz64(uint32_t off)  { return off ^ ((off >> 3) & 0x30); }

__device__ __forceinline__ void cp16(uint32_t dst, const void* src) {
    asm volatile("cp.async.cg.shared.global [%0], [%1], 16;" :: "r"(dst), "l"(src));
}
#define CP_COMMIT() asm volatile("cp.async.commit_group;" ::: "memory")
#define CP_WAIT2()  asm volatile("cp.async.wait_group 2;" ::: "memory")
#define CP_WAIT0()  asm volatile("cp.async.wait_group 0;" ::: "memory")

__device__ __forceinline__ void ldm_x4(uint32_t* r, uint32_t addr) {
    asm volatile("ldmatrix.sync.aligned.m8n8.x4.shared.b16 {%0,%1,%2,%3}, [%4];"
                 : "=r"(r[0]), "=r"(r[1]), "=r"(r[2]), "=r"(r[3]) : "r"(addr));
}
__device__ __forceinline__ void mma_f16(float* c, const uint32_t* a, const uint32_t* b) {
    asm volatile("mma.sync.aligned.m16n8k16.row.col.f32.f16.f16.f32 "
                 "{%0,%1,%2,%3},{%4,%5,%6,%7},{%8,%9},{%0,%1,%2,%3};"
                 : "+f"(c[0]), "+f"(c[1]), "+f"(c[2]), "+f"(c[3])
                 : "r"(a[0]), "r"(a[1]), "r"(a[2]), "r"(a[3]), "r"(b[0]), "r"(b[1]));
}

// ---------------- conversion kernels ----------------
__global__ void convA_kernel(const float* __restrict__ hid) {
    long i4 = (long)blockIdx.x * blockDim.x + threadIdx.x;   // over M_*K_/4
    float4 v = reinterpret_cast<const float4*>(hid)[i4];
    __half h[4] = {__float2half_rn(v.x), __float2half_rn(v.y),
                   __float2half_rn(v.z), __float2half_rn(v.w)};
    *reinterpret_cast<ushort4*>(&g_Apack[i4 * 4]) = *reinterpret_cast<ushort4*>(h);
}

__global__ void convB_kernel(const float* __restrict__ Wq,
                             const float* __restrict__ Wk,
                             const float* __restrict__ Wv) {
    __shared__ float tile[32][33];
    int k0 = blockIdx.x * 32;
    int n0 = blockIdx.y * 32;
    const float* W; int ldw, nc;
    if (n0 < NH_ * D_)               { W = Wq; ldw = NH_ * D_;  nc = n0; }
    else if (n0 < (NH_ + NKV_) * D_) { W = Wk; ldw = NKV_ * D_; nc = n0 - NH_ * D_; }
    else                             { W = Wv; ldw = NKV_ * D_; nc = n0 - (NH_ + NKV_) * D_; }
    int tx = threadIdx.x, ty = threadIdx.y;
#pragma unroll
    for (int r = 0; r < 4; r++)
        tile[ty + r * 8][tx] = W[(long)(k0 + ty + r * 8) * ldw + nc + tx];
    __syncthreads();
#pragma unroll
    for (int r = 0; r < 4; r++) {
        int nl = ty + r * 8;
        float x = tile[tx][nl];
        __half hi = __float2half_rn(x);
        __half lo = __float2half_rn(x - __half2float(hi));
        long base = (long)(n0 + nl) * KP + (k0 >> 5) * 64 + tx;
        g_Bpack[base]      = hi;
        g_Bpack[base + 32] = lo;
    }
}

// ---------------- fused GEMM + bias + RoPE (512 thr, 64x32 warp tiles) ----------------
__global__ __launch_bounds__(512, 1)
void qkv_mma_kernel(const float* __restrict__ cosp, const float* __restrict__ sinp,
                    const float* __restrict__ bq, const float* __restrict__ bk,
                    const float* __restrict__ bv, float* __restrict__ out) {
    extern __shared__ char smem[];
    const uint32_t sbase = smem_u32(smem);
    const int tid  = threadIdx.x;
    const int wid  = tid >> 5, lane = tid & 31;
    const int m0   = blockIdx.y * BM;
    const int hg   = blockIdx.x;              // one head per CTA
    const int n0   = hg * BN;

    const int warp_m = wid & 3;               // 4 warps over M (64 rows each)
    const int warp_n = wid >> 2;              // 4 warps over N (32 cols each)

    const __half* Agb = g_Apack + (long)m0 * K_;
    const __half* Bgb = g_Bpack + (long)n0 * KP;

    // stage loader: A 1024x16B (SW64) + B 1024x16B (SW128), 512 threads -> 2+2 each
    auto load_stage = [&](int c, int s) {
        const uint32_t ab = sbase + (uint32_t)(s * STAGE_BYTES);
        const uint32_t bb = ab + 16384;
        const __half* Ag = Agb + (long)c * 32;
        const __half* Bg = Bgb + (long)c * 64;
#pragma unroll
        for (int i = 0; i < 2; i++) {
            int e = tid + i * 512, row = e >> 2, q = e & 3;   // 256 rows x 4 units
            cp16(ab + swz64(row * 64 + q * 16), Ag + (long)row * K_ + q * 8);
        }
#pragma unroll
        for (int i = 0; i < 2; i++) {
            int e = tid + i * 512, row = e >> 3, q = e & 7;   // 128 rows x 8 units
            cp16(bb + swz128(row * 128 + q * 16), Bg + (long)row * KP + q * 8);
        }
    };

    float acc[4][4][4];
#pragma unroll
    for (int i = 0; i < 4; i++)
#pragma unroll
        for (int j = 0; j < 4; j++)
#pragma unroll
            for (int r = 0; r < 4; r++) acc[i][j][r] = 0.f;

    load_stage(0, 0); CP_COMMIT();
    load_stage(1, 1); CP_COMMIT();
    load_stage(2, 2); CP_COMMIT();

    const int a_row = lane & 15;
    const int a_cb  = (lane >> 4) * 16;
    const int b_row = ((lane >> 4) << 3) + (lane & 7);
    const int b_cb  = ((lane >> 3) & 1) * 16;

    for (int c = 0; c < NC; c++) {
        CP_WAIT2();
        __syncthreads();                      // stage c ready; all warps done with c-1

        if (c + 3 < NC) load_stage(c + 3, (c + 3) & 3);
        CP_COMMIT();

        const uint32_t ab = sbase + (uint32_t)((c & 3) * STAGE_BYTES);
        const uint32_t bb = ab + 16384;

#pragma unroll
        for (int ks = 0; ks < 2; ks++) {
            uint32_t af[4][4], bf[2][4];
            // A-hi fragments (64B rows, SW64)
#pragma unroll
            for (int mt = 0; mt < 4; mt++) {
                uint32_t off = (uint32_t)(warp_m * 64 + mt * 16 + a_row) * 64 + ks * 32 + a_cb;
                ldm_x4(af[mt], ab + swz64(off));
            }
            // B-hi fragments (32 cols = 2 x16 tiles)
#pragma unroll
            for (int bt = 0; bt < 2; bt++) {
                uint32_t off = (uint32_t)(warp_n * 32 + bt * 16 + b_row) * 128 + ks * 32 + b_cb;
                ldm_x4(bf[bt], bb + swz128(off));
            }
            // pass 1: a_hi * b_hi
#pragma unroll
            for (int mt = 0; mt < 4; mt++)
#pragma unroll
                for (int nt = 0; nt < 4; nt++)
                    mma_f16(acc[mt][nt], af[mt], &bf[nt >> 1][(nt & 1) * 2]);
            // B-lo (overwrite bf), pass 2: a_hi * b_lo
#pragma unroll
            for (int bt = 0; bt < 2; bt++) {
                uint32_t off = (uint32_t)(warp_n * 32 + bt * 16 + b_row) * 128 + 64 + ks * 32 + b_cb;
                ldm_x4(bf[bt], bb + swz128(off));
            }
#pragma unroll
            for (int mt = 0; mt < 4; mt++)
#pragma unroll
                for (int nt = 0; nt < 4; nt++)
                    mma_f16(acc[mt][nt], af[mt], &bf[nt >> 1][(nt & 1) * 2]);
        }
    }

    CP_WAIT0();
    __syncthreads();

    // ---- epilogue: accums -> smem stage ----
    float* stage = reinterpret_cast<float*>(smem);
#pragma unroll
    for (int mt = 0; mt < 4; mt++) {
#pragma unroll
        for (int nt = 0; nt < 4; nt++) {
            int row = warp_m * 64 + mt * 16 + (lane >> 2);
            int col = warp_n * 32 + nt * 8 + (lane & 3) * 2;
            *reinterpret_cast<float2*>(&stage[row * SROW + col]) =
                make_float2(acc[mt][nt][0], acc[mt][nt][1]);
            *reinterpret_cast<float2*>(&stage[(row + 8) * SROW + col]) =
                make_float2(acc[mt][nt][2], acc[mt][nt][3]);
        }
    }
    __syncthreads();

    // ---- bias + RoPE + coalesced store (one head) ----
    bool rope; const float* bias; float* ob; int nheads, hloc;
    if (hg < NH_)             { rope = true;  bias = bq; ob = out;                 nheads = NH_;  hloc = hg; }
    else if (hg < NH_ + NKV_) { rope = true;  bias = bk; ob = out + QSIZE;         nheads = NKV_; hloc = hg - NH_; }
    else                      { rope = false; bias = bv; ob = out + QSIZE + KSIZE; nheads = NKV_; hloc = hg - NH_ - NKV_; }

    const int j0 = lane * 4;                 // own columns
    const int p0 = (j0 + 64) & 127;          // partner columns
    const int d  = j0 & 63;
    float4 bo = *reinterpret_cast<const float4*>(bias + hloc * D_ + j0);
    float4 bp = *reinterpret_cast<const float4*>(bias + hloc * D_ + p0);

    for (int r = 0; r < 16; r++) {
        int row = wid * 16 + r;              // 16 warps x 16 rows = 256
        int m2 = m0 + row;
        int bi = m2 >> 12, sq = m2 & (S_ - 1);
        float4 own = *reinterpret_cast<const float4*>(&stage[row * SROW + j0]);
        float4 par = *reinterpret_cast<const float4*>(&stage[row * SROW + p0]);
        own.x += bo.x; own.y += bo.y; own.z += bo.z; own.w += bo.w;
        par.x += bp.x; par.y += bp.y; par.z += bp.z; par.w += bp.w;
        float4 o;
        if (rope) {
            float4 cc = *reinterpret_cast<const float4*>(cosp + (long)m2 * D_ + d);
            float4 ss = *reinterpret_cast<const float4*>(sinp + (long)m2 * D_ + d);
            if (lane < 16) {   // own = lo half: o = lo*c - hi*s
                o.x = own.x * cc.x - par.x * ss.x;
                o.y = own.y * cc.y - par.y * ss.y;
                o.z = own.z * cc.z - par.z * ss.z;
                o.w = own.w * cc.w - par.w * ss.w;
            } else {           // own = hi half: o = hi*c + lo*s
                o.x = own.x * cc.x + par.x * ss.x;
                o.y = own.y * cc.y + par.y * ss.y;
                o.z = own.z * cc.z + par.z * ss.z;
                o.w = own.w * cc.w + par.w * ss.w;
            }
        } else {
            o = own;
        }
        float* optr = ob + ((long)(bi * nheads + hloc) * S_ + sq) * D_;
        *reinterpret_cast<float4*>(optr + j0) = o;
    }
}

// ---------------- launch ----------------
extern "C" void kernel_launch(void* const* d_in, const int* in_sizes, int n_in,
                              void* d_out, int out_size) {
    (void)in_sizes; (void)n_in; (void)out_size;
    const float* hid  = (const float*)d_in[0];
    const float* cosp = (const float*)d_in[1];
    const float* sinp = (const float*)d_in[2];
    const float* Wq   = (const float*)d_in[3];
    const float* bq   = (const float*)d_in[4];
    const float* Wk   = (const float*)d_in[5];
    const float* bk   = (const float*)d_in[6];
    const float* Wv   = (const float*)d_in[7];
    const float* bv   = (const float*)d_in[8];
    float* out = (float*)d_out;

    cudaFuncSetAttribute(qkv_mma_kernel, cudaFuncAttributeMaxDynamicSharedMemorySize, SMEM_TOTAL);

    convA_kernel<<<(M_ * K_ / 4) / 256, 256>>>(hid);
    convB_kernel<<<dim3(K_ / 32, NTOT / 32), dim3(32, 8)>>>(Wq, Wk, Wv);
    qkv_mma_kernel<<<dim3(NTOT / BN, M_ / BM), 512, SMEM_TOTAL>>>(cosp, sinp, bq, bk, bv, out);
}

// round 7
// speedup vs baseline: 4.7875x; 1.1264x over previous
#include <cuda_runtime.h>
#include <cuda_fp16.h>
#include <cstdint>

#define B_ 2
#define S_ 4096
#define H_ 3584
#define NH_ 28
#define NKV_ 4
#define D_ 128

constexpr int M_   = B_ * S_;                 // 8192
constexpr int K_   = H_;                      // 3584
constexpr int NTOT = (NH_ + 2 * NKV_) * D_;   // 4608
constexpr int KP   = 2 * K_;                  // B packed cols (hi|lo per 32-block)
constexpr long QSIZE = (long)B_ * NH_ * S_ * D_;
constexpr long KSIZE = (long)B_ * NKV_ * S_ * D_;

constexpr int BM = 128, BN = 128;
constexpr int NC = K_ / 32;                   // 112 chunks of 32 real K
constexpr int NSTAGE = 4;
constexpr int STAGE_BYTES = 24576;            // A 8KB (128x64B) + B 16KB (128x128B)
constexpr int A_BYTES = 8192;
constexpr int SROW = 132;
constexpr int SMEM_TOTAL = (NSTAGE * STAGE_BYTES > BM * SROW * 4)
                         ? NSTAGE * STAGE_BYTES : BM * SROW * 4;  // 98304

// ---------------- scratch ----------------
__device__ __half g_Apack[(long)M_ * K_];     // plain [m][k] fp16 (hi only)
__device__ __half g_Bpack[(long)NTOT * KP];   // [n][blk*64 + islo*32 + pos] fp16 hi|lo

// ---------------- helpers ----------------
__device__ __forceinline__ uint32_t smem_u32(const void* p) {
    uint32_t a;
    asm("{ .reg .u64 t; cvta.to.shared.u64 t, %1; cvt.u32.u64 %0, t; }" : "=r"(a) : "l"(p));
    return a;
}
__device__ __forceinline__ uint32_t swz128(uint32_t off) { return off ^ ((off >> 3) & 0x70); }
__device__ __forceinline__ uint32_t swz64(uint32_t off)  { return off ^ ((off >> 3) & 0x30); }

__device__ __forceinline__ void cp16(uint32_t dst, const void* src) {
    asm volatile("cp.async.cg.shared.global [%0], [%1], 16;" :: "r"(dst), "l"(src));
}
#define CP_COMMIT() asm volatile("cp.async.commit_group;" ::: "memory")
#define CP_WAIT2()  asm volatile("cp.async.wait_group 2;" ::: "memory")
#define CP_WAIT0()  asm volatile("cp.async.wait_group 0;" ::: "memory")

__device__ __forceinline__ void ldm_x4(uint32_t* r, uint32_t addr) {
    asm volatile("ldmatrix.sync.aligned.m8n8.x4.shared.b16 {%0,%1,%2,%3}, [%4];"
                 : "=r"(r[0]), "=r"(r[1]), "=r"(r[2]), "=r"(r[3]) : "r"(addr));
}
__device__ __forceinline__ void mma_f16(float* c, const uint32_t* a, const uint32_t* b) {
    asm volatile("mma.sync.aligned.m16n8k16.row.col.f32.f16.f16.f32 "
                 "{%0,%1,%2,%3},{%4,%5,%6,%7},{%8,%9},{%0,%1,%2,%3};"
                 : "+f"(c[0]), "+f"(c[1]), "+f"(c[2]), "+f"(c[3])
                 : "r"(a[0]), "r"(a[1]), "r"(a[2]), "r"(a[3]), "r"(b[0]), "r"(b[1]));
}

// ---------------- conversion kernels ----------------
__global__ void convA_kernel(const float* __restrict__ hid) {
    long i4 = (long)blockIdx.x * blockDim.x + threadIdx.x;   // over M_*K_/4
    float4 v = reinterpret_cast<const float4*>(hid)[i4];
    __half h[4] = {__float2half_rn(v.x), __float2half_rn(v.y),
                   __float2half_rn(v.z), __float2half_rn(v.w)};
    *reinterpret_cast<ushort4*>(&g_Apack[i4 * 4]) = *reinterpret_cast<ushort4*>(h);
}

__global__ void convB_kernel(const float* __restrict__ Wq,
                             const float* __restrict__ Wk,
                             const float* __restrict__ Wv) {
    __shared__ float tile[32][33];
    int k0 = blockIdx.x * 32;
    int n0 = blockIdx.y * 32;
    const float* W; int ldw, nc;
    if (n0 < NH_ * D_)               { W = Wq; ldw = NH_ * D_;  nc = n0; }
    else if (n0 < (NH_ + NKV_) * D_) { W = Wk; ldw = NKV_ * D_; nc = n0 - NH_ * D_; }
    else                             { W = Wv; ldw = NKV_ * D_; nc = n0 - (NH_ + NKV_) * D_; }
    int tx = threadIdx.x, ty = threadIdx.y;
#pragma unroll
    for (int r = 0; r < 4; r++)
        tile[ty + r * 8][tx] = W[(long)(k0 + ty + r * 8) * ldw + nc + tx];
    __syncthreads();
#pragma unroll
    for (int r = 0; r < 4; r++) {
        int nl = ty + r * 8;
        float x = tile[tx][nl];
        __half hi = __float2half_rn(x);
        __half lo = __float2half_rn(x - __half2float(hi));
        long base = (long)(n0 + nl) * KP + (k0 >> 5) * 64 + tx;
        g_Bpack[base]      = hi;
        g_Bpack[base + 32] = lo;
    }
}

// ---------------- fused GEMM + bias + RoPE (128 thr, 2 CTA/SM, 64x64 warp tiles) ----------------
__global__ __launch_bounds__(128, 2)
void qkv_mma_kernel(const float* __restrict__ cosp, const float* __restrict__ sinp,
                    const float* __restrict__ bq, const float* __restrict__ bk,
                    const float* __restrict__ bv, float* __restrict__ out) {
    extern __shared__ char smem[];
    const uint32_t sbase = smem_u32(smem);
    const int tid  = threadIdx.x;
    const int wid  = tid >> 5, lane = tid & 31;
    const int m0   = blockIdx.y * BM;
    const int hg   = blockIdx.x;              // one head per CTA
    const int n0   = hg * BN;

    const int warp_m = wid & 1;               // 2 warps over M (64 rows each)
    const int warp_n = wid >> 1;              // 2 warps over N (64 cols each)

    const __half* Agb = g_Apack + (long)m0 * K_;
    const __half* Bgb = g_Bpack + (long)n0 * KP;

    // stage loader: A 512x16B (SW64) + B 1024x16B (SW128), 128 threads -> 4+8 each
    auto load_stage = [&](int c, int s) {
        const uint32_t ab = sbase + (uint32_t)(s * STAGE_BYTES);
        const uint32_t bb = ab + A_BYTES;
        const __half* Ag = Agb + (long)c * 32;
        const __half* Bg = Bgb + (long)c * 64;
#pragma unroll
        for (int i = 0; i < 4; i++) {
            int e = tid + i * 128, row = e >> 2, q = e & 3;   // 128 rows x 4 units
            cp16(ab + swz64(row * 64 + q * 16), Ag + (long)row * K_ + q * 8);
        }
#pragma unroll
        for (int i = 0; i < 8; i++) {
            int e = tid + i * 128, row = e >> 3, q = e & 7;   // 128 rows x 8 units
            cp16(bb + swz128(row * 128 + q * 16), Bg + (long)row * KP + q * 8);
        }
    };

    float acc[4][8][4];
#pragma unroll
    for (int i = 0; i < 4; i++)
#pragma unroll
        for (int j = 0; j < 8; j++)
#pragma unroll
            for (int r = 0; r < 4; r++) acc[i][j][r] = 0.f;

    load_stage(0, 0); CP_COMMIT();
    load_stage(1, 1); CP_COMMIT();
    load_stage(2, 2); CP_COMMIT();

    const int a_row = lane & 15;
    const int a_cb  = (lane >> 4) * 16;
    const int b_row = ((lane >> 4) << 3) + (lane & 7);
    const int b_cb  = ((lane >> 3) & 1) * 16;

    for (int c = 0; c < NC; c++) {
        CP_WAIT2();
        __syncthreads();                      // stage c ready; all warps done with c-1

        if (c + 3 < NC) load_stage(c + 3, (c + 3) & 3);
        CP_COMMIT();

        const uint32_t ab = sbase + (uint32_t)((c & 3) * STAGE_BYTES);
        const uint32_t bb = ab + A_BYTES;

#pragma unroll
        for (int ks = 0; ks < 2; ks++) {
            uint32_t af[4][4], bf[4][4];
            // A-hi fragments (64B rows, SW64)
#pragma unroll
            for (int mt = 0; mt < 4; mt++) {
                uint32_t off = (uint32_t)(warp_m * 64 + mt * 16 + a_row) * 64 + ks * 32 + a_cb;
                ldm_x4(af[mt], ab + swz64(off));
            }
            // B-hi fragments (64 cols = 4 x16 tiles)
#pragma unroll
            for (int bt = 0; bt < 4; bt++) {
                uint32_t off = (uint32_t)(warp_n * 64 + bt * 16 + b_row) * 128 + ks * 32 + b_cb;
                ldm_x4(bf[bt], bb + swz128(off));
            }
            // pass 1: a_hi * b_hi
#pragma unroll
            for (int mt = 0; mt < 4; mt++)
#pragma unroll
                for (int nt = 0; nt < 8; nt++)
                    mma_f16(acc[mt][nt], af[mt], &bf[nt >> 1][(nt & 1) * 2]);
            // B-lo (overwrite bf), pass 2: a_hi * b_lo
#pragma unroll
            for (int bt = 0; bt < 4; bt++) {
                uint32_t off = (uint32_t)(warp_n * 64 + bt * 16 + b_row) * 128 + 64 + ks * 32 + b_cb;
                ldm_x4(bf[bt], bb + swz128(off));
            }
#pragma unroll
            for (int mt = 0; mt < 4; mt++)
#pragma unroll
                for (int nt = 0; nt < 8; nt++)
                    mma_f16(acc[mt][nt], af[mt], &bf[nt >> 1][(nt & 1) * 2]);
        }
    }

    CP_WAIT0();
    __syncthreads();

    // ---- epilogue: accums -> smem stage ----
    float* stage = reinterpret_cast<float*>(smem);
#pragma unroll
    for (int mt = 0; mt < 4; mt++) {
#pragma unroll
        for (int nt = 0; nt < 8; nt++) {
            int row = warp_m * 64 + mt * 16 + (lane >> 2);
            int col = warp_n * 64 + nt * 8 + (lane & 3) * 2;
            *reinterpret_cast<float2*>(&stage[row * SROW + col]) =
                make_float2(acc[mt][nt][0], acc[mt][nt][1]);
            *reinterpret_cast<float2*>(&stage[(row + 8) * SROW + col]) =
                make_float2(acc[mt][nt][2], acc[mt][nt][3]);
        }
    }
    __syncthreads();

    // ---- bias + RoPE + coalesced store (one head) ----
    bool rope; const float* bias; float* ob; int nheads, hloc;
    if (hg < NH_)             { rope = true;  bias = bq; ob = out;                 nheads = NH_;  hloc = hg; }
    else if (hg < NH_ + NKV_) { rope = true;  bias = bk; ob = out + QSIZE;         nheads = NKV_; hloc = hg - NH_; }
    else                      { rope = false; bias = bv; ob = out + QSIZE + KSIZE; nheads = NKV_; hloc = hg - NH_ - NKV_; }

    const int j0 = lane * 4;                 // own columns
    const int p0 = (j0 + 64) & 127;          // partner columns
    const int d  = j0 & 63;
    float4 bo = *reinterpret_cast<const float4*>(bias + hloc * D_ + j0);
    float4 bp = *reinterpret_cast<const float4*>(bias + hloc * D_ + p0);

    for (int r = 0; r < 32; r++) {
        int row = wid * 32 + r;              // 4 warps x 32 rows = 128
        int m2 = m0 + row;
        int bi = m2 >> 12, sq = m2 & (S_ - 1);
        float4 own = *reinterpret_cast<const float4*>(&stage[row * SROW + j0]);
        float4 par = *reinterpret_cast<const float4*>(&stage[row * SROW + p0]);
        own.x += bo.x; own.y += bo.y; own.z += bo.z; own.w += bo.w;
        par.x += bp.x; par.y += bp.y; par.z += bp.z; par.w += bp.w;
        float4 o;
        if (rope) {
            float4 cc = *reinterpret_cast<const float4*>(cosp + (long)m2 * D_ + d);
            float4 ss = *reinterpret_cast<const float4*>(sinp + (long)m2 * D_ + d);
            if (lane < 16) {   // own = lo half: o = lo*c - hi*s
                o.x = own.x * cc.x - par.x * ss.x;
                o.y = own.y * cc.y - par.y * ss.y;
                o.z = own.z * cc.z - par.z * ss.z;
                o.w = own.w * cc.w - par.w * ss.w;
            } else {           // own = hi half: o = hi*c + lo*s
                o.x = own.x * cc.x + par.x * ss.x;
                o.y = own.y * cc.y + par.y * ss.y;
                o.z = own.z * cc.z + par.z * ss.z;
                o.w = own.w * cc.w + par.w * ss.w;
            }
        } else {
            o = own;
        }
        float* optr = ob + ((long)(bi * nheads + hloc) * S_ + sq) * D_;
        *reinterpret_cast<float4*>(optr + j0) = o;
    }
}

// ---------------- launch ----------------
extern "C" void kernel_launch(void* const* d_in, const int* in_sizes, int n_in,
                              void* d_out, int out_size) {
    (void)in_sizes; (void)n_in; (void)out_size;
    const float* hid  = (const float*)d_in[0];
    const float* cosp = (const float*)d_in[1];
    const float* sinp = (const float*)d_in[2];
    const float* Wq   = (const float*)d_in[3];
    const float* bq   = (const float*)d_in[4];
    const float* Wk   = (const float*)d_in[5];
    const float* bk   = (const float*)d_in[6];
    const float* Wv   = (const float*)d_in[7];
    const float* bv   = (const float*)d_in[8];
    float* out = (float*)d_out;

    cudaFuncSetAttribute(qkv_mma_kernel, cudaFuncAttributeMaxDynamicSharedMemorySize, SMEM_TOTAL);

    convA_kernel<<<(M_ * K_ / 4) / 256, 256>>>(hid);
    convB_kernel<<<dim3(K_ / 32, NTOT / 32), dim3(32, 8)>>>(Wq, Wk, Wv);
    qkv_mma_kernel<<<dim3(NTOT / BN, M_ / BM), 128, SMEM_TOTAL>>>(cosp, sinp, bq, bk, bv, out);
}

// round 8
// speedup vs baseline: 8.5882x; 1.7939x over previous
#include <cuda_runtime.h>
#include <cuda_fp16.h>
#include <cstdint>

#define B_ 2
#define S_ 4096
#define H_ 3584
#define NH_ 28
#define NKV_ 4
#define D_ 128

constexpr int M_   = B_ * S_;                 // 8192
constexpr int K_   = H_;                      // 3584
constexpr int NTOT = (NH_ + 2 * NKV_) * D_;   // 4608
constexpr long QSIZE = (long)B_ * NH_ * S_ * D_;
constexpr long KSIZE = (long)B_ * NKV_ * S_ * D_;

constexpr int BM = 128, BN = 128;
constexpr int NC = K_ / 32;                   // 112 chunks of 32 K
constexpr int NSTAGE = 4;
constexpr int STAGE_BYTES = 16384;            // A 8KB (128x64B) + B 8KB (128x64B)
constexpr int A_BYTES = 8192;
constexpr int SROW = 132;
constexpr int SMEM_TOTAL = (NSTAGE * STAGE_BYTES > BM * SROW * 4)
                         ? NSTAGE * STAGE_BYTES : BM * SROW * 4;  // 67584

// ---------------- scratch ----------------
__device__ __half g_Apack[(long)M_ * K_];     // [m][k] fp16
__device__ __half g_Bpack[(long)NTOT * K_];   // [n][k] fp16

// ---------------- helpers ----------------
__device__ __forceinline__ uint32_t smem_u32(const void* p) {
    uint32_t a;
    asm("{ .reg .u64 t; cvta.to.shared.u64 t, %1; cvt.u32.u64 %0, t; }" : "=r"(a) : "l"(p));
    return a;
}
__device__ __forceinline__ uint32_t swz64(uint32_t off)  { return off ^ ((off >> 3) & 0x30); }

__device__ __forceinline__ void cp16(uint32_t dst, const void* src) {
    asm volatile("cp.async.cg.shared.global [%0], [%1], 16;" :: "r"(dst), "l"(src));
}
#define CP_COMMIT() asm volatile("cp.async.commit_group;" ::: "memory")
#define CP_WAIT2()  asm volatile("cp.async.wait_group 2;" ::: "memory")
#define CP_WAIT0()  asm volatile("cp.async.wait_group 0;" ::: "memory")

__device__ __forceinline__ void ldm_x4(uint32_t* r, uint32_t addr) {
    asm volatile("ldmatrix.sync.aligned.m8n8.x4.shared.b16 {%0,%1,%2,%3}, [%4];"
                 : "=r"(r[0]), "=r"(r[1]), "=r"(r[2]), "=r"(r[3]) : "r"(addr));
}
__device__ __forceinline__ void mma_f16(float* c, const uint32_t* a, const uint32_t* b) {
    asm volatile("mma.sync.aligned.m16n8k16.row.col.f32.f16.f16.f32 "
                 "{%0,%1,%2,%3},{%4,%5,%6,%7},{%8,%9},{%0,%1,%2,%3};"
                 : "+f"(c[0]), "+f"(c[1]), "+f"(c[2]), "+f"(c[3])
                 : "r"(a[0]), "r"(a[1]), "r"(a[2]), "r"(a[3]), "r"(b[0]), "r"(b[1]));
}

// ---------------- conversion kernels ----------------
__global__ void convA_kernel(const float* __restrict__ hid) {
    long i4 = (long)blockIdx.x * blockDim.x + threadIdx.x;   // over M_*K_/4
    float4 v = reinterpret_cast<const float4*>(hid)[i4];
    __half h[4] = {__float2half_rn(v.x), __float2half_rn(v.y),
                   __float2half_rn(v.z), __float2half_rn(v.w)};
    *reinterpret_cast<ushort4*>(&g_Apack[i4 * 4]) = *reinterpret_cast<ushort4*>(h);
}

__global__ void convB_kernel(const float* __restrict__ Wq,
                             const float* __restrict__ Wk,
                             const float* __restrict__ Wv) {
    __shared__ float tile[32][33];
    int k0 = blockIdx.x * 32;
    int n0 = blockIdx.y * 32;
    const float* W; int ldw, nc;
    if (n0 < NH_ * D_)               { W = Wq; ldw = NH_ * D_;  nc = n0; }
    else if (n0 < (NH_ + NKV_) * D_) { W = Wk; ldw = NKV_ * D_; nc = n0 - NH_ * D_; }
    else                             { W = Wv; ldw = NKV_ * D_; nc = n0 - (NH_ + NKV_) * D_; }
    int tx = threadIdx.x, ty = threadIdx.y;
#pragma unroll
    for (int r = 0; r < 4; r++)
        tile[ty + r * 8][tx] = W[(long)(k0 + ty + r * 8) * ldw + nc + tx];
    __syncthreads();
#pragma unroll
    for (int r = 0; r < 4; r++) {
        int nl = ty + r * 8;
        g_Bpack[(long)(n0 + nl) * K_ + k0 + tx] = __float2half_rn(tile[tx][nl]);
    }
}

// ---------------- fused GEMM + bias + RoPE (128 thr, 2 CTA/SM, 64x64 warp tiles) ----------------
__global__ __launch_bounds__(128, 2)
void qkv_mma_kernel(const float* __restrict__ cosp, const float* __restrict__ sinp,
                    const float* __restrict__ bq, const float* __restrict__ bk,
                    const float* __restrict__ bv, float* __restrict__ out) {
    extern __shared__ char smem[];
    const uint32_t sbase = smem_u32(smem);
    const int tid  = threadIdx.x;
    const int wid  = tid >> 5, lane = tid & 31;
    const int m0   = blockIdx.y * BM;
    const int hg   = blockIdx.x;              // one head per CTA
    const int n0   = hg * BN;

    const int warp_m = wid & 1;               // 2 warps over M (64 rows each)
    const int warp_n = wid >> 1;              // 2 warps over N (64 cols each)

    const __half* Agb = g_Apack + (long)m0 * K_;
    const __half* Bgb = g_Bpack + (long)n0 * K_;

    // stage loader: A 512x16B + B 512x16B (both SW64), 128 threads -> 4+4 each
    auto load_stage = [&](int c, int s) {
        const uint32_t ab = sbase + (uint32_t)(s * STAGE_BYTES);
        const uint32_t bb = ab + A_BYTES;
        const __half* Ag = Agb + (long)c * 32;
        const __half* Bg = Bgb + (long)c * 32;
#pragma unroll
        for (int i = 0; i < 4; i++) {
            int e = tid + i * 128, row = e >> 2, q = e & 3;   // 128 rows x 4 units
            cp16(ab + swz64(row * 64 + q * 16), Ag + (long)row * K_ + q * 8);
        }
#pragma unroll
        for (int i = 0; i < 4; i++) {
            int e = tid + i * 128, row = e >> 2, q = e & 3;
            cp16(bb + swz64(row * 64 + q * 16), Bg + (long)row * K_ + q * 8);
        }
    };

    float acc[4][8][4];
#pragma unroll
    for (int i = 0; i < 4; i++)
#pragma unroll
        for (int j = 0; j < 8; j++)
#pragma unroll
            for (int r = 0; r < 4; r++) acc[i][j][r] = 0.f;

    load_stage(0, 0); CP_COMMIT();
    load_stage(1, 1); CP_COMMIT();
    load_stage(2, 2); CP_COMMIT();

    const int a_row = lane & 15;
    const int a_cb  = (lane >> 4) * 16;
    const int b_row = ((lane >> 4) << 3) + (lane & 7);
    const int b_cb  = ((lane >> 3) & 1) * 16;

    for (int c = 0; c < NC; c++) {
        CP_WAIT2();
        __syncthreads();                      // stage c ready; all warps done with c-1

        if (c + 3 < NC) load_stage(c + 3, (c + 3) & 3);
        CP_COMMIT();

        const uint32_t ab = sbase + (uint32_t)((c & 3) * STAGE_BYTES);
        const uint32_t bb = ab + A_BYTES;

#pragma unroll
        for (int ks = 0; ks < 2; ks++) {
            uint32_t af[4][4], bf[4][4];
#pragma unroll
            for (int mt = 0; mt < 4; mt++) {
                uint32_t off = (uint32_t)(warp_m * 64 + mt * 16 + a_row) * 64 + ks * 32 + a_cb;
                ldm_x4(af[mt], ab + swz64(off));
            }
#pragma unroll
            for (int bt = 0; bt < 4; bt++) {
                uint32_t off = (uint32_t)(warp_n * 64 + bt * 16 + b_row) * 64 + ks * 32 + b_cb;
                ldm_x4(bf[bt], bb + swz64(off));
            }
#pragma unroll
            for (int mt = 0; mt < 4; mt++)
#pragma unroll
                for (int nt = 0; nt < 8; nt++)
                    mma_f16(acc[mt][nt], af[mt], &bf[nt >> 1][(nt & 1) * 2]);
        }
    }

    CP_WAIT0();
    __syncthreads();

    // ---- epilogue: accums -> smem stage ----
    float* stage = reinterpret_cast<float*>(smem);
#pragma unroll
    for (int mt = 0; mt < 4; mt++) {
#pragma unroll
        for (int nt = 0; nt < 8; nt++) {
            int row = warp_m * 64 + mt * 16 + (lane >> 2);
            int col = warp_n * 64 + nt * 8 + (lane & 3) * 2;
            *reinterpret_cast<float2*>(&stage[row * SROW + col]) =
                make_float2(acc[mt][nt][0], acc[mt][nt][1]);
            *reinterpret_cast<float2*>(&stage[(row + 8) * SROW + col]) =
                make_float2(acc[mt][nt][2], acc[mt][nt][3]);
        }
    }
    __syncthreads();

    // ---- bias + RoPE + coalesced store (one head) ----
    bool rope; const float* bias; float* ob; int nheads, hloc;
    if (hg < NH_)             { rope = true;  bias = bq; ob = out;                 nheads = NH_;  hloc = hg; }
    else if (hg < NH_ + NKV_) { rope = true;  bias = bk; ob = out + QSIZE;         nheads = NKV_; hloc = hg - NH_; }
    else                      { rope = false; bias = bv; ob = out + QSIZE + KSIZE; nheads = NKV_; hloc = hg - NH_ - NKV_; }

    const int j0 = lane * 4;                 // own columns
    const int p0 = (j0 + 64) & 127;          // partner columns
    const int d  = j0 & 63;
    float4 bo = *reinterpret_cast<const float4*>(bias + hloc * D_ + j0);
    float4 bp = *reinterpret_cast<const float4*>(bias + hloc * D_ + p0);

    for (int r = 0; r < 32; r++) {
        int row = wid * 32 + r;              // 4 warps x 32 rows = 128
        int m2 = m0 + row;
        int bi = m2 >> 12, sq = m2 & (S_ - 1);
        float4 own = *reinterpret_cast<const float4*>(&stage[row * SROW + j0]);
        float4 par = *reinterpret_cast<const float4*>(&stage[row * SROW + p0]);
        own.x += bo.x; own.y += bo.y; own.z += bo.z; own.w += bo.w;
        par.x += bp.x; par.y += bp.y; par.z += bp.z; par.w += bp.w;
        float4 o;
        if (rope) {
            float4 cc = *reinterpret_cast<const float4*>(cosp + (long)m2 * D_ + d);
            float4 ss = *reinterpret_cast<const float4*>(sinp + (long)m2 * D_ + d);
            if (lane < 16) {   // own = lo half: o = lo*c - hi*s
                o.x = own.x * cc.x - par.x * ss.x;
                o.y = own.y * cc.y - par.y * ss.y;
                o.z = own.z * cc.z - par.z * ss.z;
                o.w = own.w * cc.w - par.w * ss.w;
            } else {           // own = hi half: o = hi*c + lo*s
                o.x = own.x * cc.x + par.x * ss.x;
                o.y = own.y * cc.y + par.y * ss.y;
                o.z = own.z * cc.z + par.z * ss.z;
                o.w = own.w * cc.w + par.w * ss.w;
            }
        } else {
            o = own;
        }
        float* optr = ob + ((long)(bi * nheads + hloc) * S_ + sq) * D_;
        *reinterpret_cast<float4*>(optr + j0) = o;
    }
}

// ---------------- launch ----------------
extern "C" void kernel_launch(void* const* d_in, const int* in_sizes, int n_in,
                              void* d_out, int out_size) {
    (void)in_sizes; (void)n_in; (void)out_size;
    const float* hid  = (const float*)d_in[0];
    const float* cosp = (const float*)d_in[1];
    const float* sinp = (const float*)d_in[2];
    const float* Wq   = (const float*)d_in[3];
    const float* bq   = (const float*)d_in[4];
    const float* Wk   = (const float*)d_in[5];
    const float* bk   = (const float*)d_in[6];
    const float* Wv   = (const float*)d_in[7];
    const float* bv   = (const float*)d_in[8];
    float* out = (float*)d_out;

    cudaFuncSetAttribute(qkv_mma_kernel, cudaFuncAttributeMaxDynamicSharedMemorySize, SMEM_TOTAL);

    convA_kernel<<<(M_ * K_ / 4) / 256, 256>>>(hid);
    convB_kernel<<<dim3(K_ / 32, NTOT / 32), dim3(32, 8)>>>(Wq, Wk, Wv);
    qkv_mma_kernel<<<dim3(NTOT / BN, M_ / BM), 128, SMEM_TOTAL>>>(cosp, sinp, bq, bk, bv, out);
}